// round 1
// baseline (speedup 1.0000x reference)
#include <cuda_runtime.h>
#include <cstdint>

// ---------------------------------------------------------------------------
// Boltzmann collision operator, spectral method.
//   N=48 grid, B=8 batches, M=5 -> t=20 angular modes.
//   Q = scale * Re( sum_t FFT(fs*phi_t)*FFT(fs*psi_t) - FFT(fs*phipsi)*FFT(fs) )
//   fs = fftshift(FFT3(f))/N^3  (fftshift folded into (-1)^(x+y+z) input flip)
// 344 complex 48^3 FFTs total. Hand-rolled mixed-radix 48 = 6 x 8.
// ---------------------------------------------------------------------------

#define NN    48
#define N2P   (NN*NN)        // 2304
#define N3    (NN*NN*NN)     // 110592
#define NB    8
#define NT    20             // angular modes
#define NJ    42             // 20 phi + 20 psi + phipsi + identity
#define LDP   49             // padded smem row (float2 units)
#define NTHR  384
#define PI_F  3.14159265358979323846f

// scratch (allowed: __device__ globals, no runtime alloc)
__device__ float2 g_spec[NB * N3];                 // ~7 MB
__device__ float2 g_S[(size_t)NB * NJ * N3];       // ~297 MB

__device__ __forceinline__ float2 cadd(float2 a, float2 b){ return make_float2(a.x+b.x, a.y+b.y); }
__device__ __forceinline__ float2 csub(float2 a, float2 b){ return make_float2(a.x-b.x, a.y-b.y); }
__device__ __forceinline__ float2 cmul(float2 a, float2 b){
    return make_float2(a.x*b.x - a.y*b.y, a.x*b.y + a.y*b.x);
}

// forward DFT3 (omega = e^{-2pi i/3})
__device__ __forceinline__ void dft3(float2 a, float2 b, float2 c,
                                     float2& X0, float2& X1, float2& X2){
    float2 t1 = cadd(b, c);
    X0 = cadd(a, t1);
    float2 m = make_float2(a.x - 0.5f*t1.x, a.y - 0.5f*t1.y);
    const float K = 0.8660254037844386f;
    float2 s = make_float2(K*(b.x - c.x), K*(b.y - c.y));
    X1 = make_float2(m.x + s.y, m.y - s.x);   // m - i*s
    X2 = make_float2(m.x - s.y, m.y + s.x);   // m + i*s
}

// 48 forward FFTs of length 48 over a 48x48 plane held in smem.
// Element e of line l lives at s[l*LDL + e*LDR].
// Decomposition: n = 8*n1 + n2 ; k = k1 + 6*k2 ;
//   stage A: per n2, DFT6 over n1 (stride 8), twiddle w48^{n2*k1}, store at 8*k1+n2
//   stage B: per k1, DFT8 over n2 (read-sync-write, in place)
// tw[n2*6 + k1] = e^{-2pi i n2 k1 / 48}
template <int LDR, int LDL>
__device__ void fft_lines(float2* s, const float2* tw){
    const int w = threadIdx.x;
    // ---- stage A: 48 lines * 8 items = 384 threads ----
    {
        int line = w >> 3, n2 = w & 7;
        float2* base = s + line*LDL + n2*LDR;
        float2 x0 = base[0*8*LDR], x1 = base[1*8*LDR], x2 = base[2*8*LDR];
        float2 x3 = base[3*8*LDR], x4 = base[4*8*LDR], x5 = base[5*8*LDR];
        float2 E0,E1,E2, O0,O1,O2;
        dft3(x0, x2, x4, E0, E1, E2);
        dft3(x1, x3, x5, O0, O1, O2);
        const float K = 0.8660254037844386f;
        float2 o1 = cmul(O1, make_float2( 0.5f, -K));   // w6^1
        float2 o2 = cmul(O2, make_float2(-0.5f, -K));   // w6^2
        float2 y0 = cadd(E0, O0), y3 = csub(E0, O0);
        float2 y1 = cadd(E1, o1), y4 = csub(E1, o1);
        float2 y2 = cadd(E2, o2), y5 = csub(E2, o2);
        const float2* t = tw + n2*6;
        y1 = cmul(y1, t[1]); y2 = cmul(y2, t[2]); y3 = cmul(y3, t[3]);
        y4 = cmul(y4, t[4]); y5 = cmul(y5, t[5]);
        base[0*8*LDR] = y0; base[1*8*LDR] = y1; base[2*8*LDR] = y2;
        base[3*8*LDR] = y3; base[4*8*LDR] = y4; base[5*8*LDR] = y5;
    }
    __syncthreads();
    // ---- stage B: 48 lines * 6 items = 288 threads ----
    {
        int line = w % 48, k1 = w / 48;
        bool act = (w < 288);
        float2 r0,r1,r2,r3,r4,r5,r6,r7;
        float2* base = s + line*LDL + (k1*8)*LDR;
        if (act){
            r0 = base[0*LDR]; r1 = base[1*LDR]; r2 = base[2*LDR]; r3 = base[3*LDR];
            r4 = base[4*LDR]; r5 = base[5*LDR]; r6 = base[6*LDR]; r7 = base[7*LDR];
        }
        __syncthreads();   // all stage-B reads complete before any write (in place)
        if (act){
            // DFT8 forward
            float2 t0 = cadd(r0,r4), t1 = csub(r0,r4), t2 = cadd(r2,r6), t3 = csub(r2,r6);
            float2 E0 = cadd(t0,t2), E2 = csub(t0,t2);
            float2 E1 = make_float2(t1.x + t3.y, t1.y - t3.x);
            float2 E3 = make_float2(t1.x - t3.y, t1.y + t3.x);
            float2 u0 = cadd(r1,r5), u1 = csub(r1,r5), u2 = cadd(r3,r7), u3 = csub(r3,r7);
            float2 Q0 = cadd(u0,u2), Q2 = csub(u0,u2);
            float2 Q1 = make_float2(u1.x + u3.y, u1.y - u3.x);
            float2 Q3 = make_float2(u1.x - u3.y, u1.y + u3.x);
            const float S2 = 0.7071067811865476f;
            float2 p1 = cmul(Q1, make_float2( S2, -S2));  // w8^1
            float2 p2 = make_float2(Q2.y, -Q2.x);          // w8^2 = -i
            float2 p3 = cmul(Q3, make_float2(-S2, -S2));   // w8^3
            float2* out = s + line*LDL + k1*LDR;
            out[ 0*LDR] = cadd(E0,Q0);
            out[ 6*LDR] = cadd(E1,p1);
            out[12*LDR] = cadd(E2,p2);
            out[18*LDR] = cadd(E3,p3);
            out[24*LDR] = csub(E0,Q0);
            out[30*LDR] = csub(E1,p1);
            out[36*LDR] = csub(E2,p2);
            out[42*LDR] = csub(E3,p3);
        }
        __syncthreads();
    }
}

__device__ __forceinline__ void init_tw(float2* tw){
    if (threadIdx.x < 48){
        int n2 = threadIdx.x / 6, k1 = threadIdx.x % 6;
        float sv, cv;
        sincosf(-2.0f*PI_F * (float)(n2*k1) / 48.0f, &sv, &cv);
        tw[threadIdx.x] = make_float2(cv, sv);
    }
}

// K1: f * (-1)^(x+y+z), FFT along z then y; one (y,z) plane per CTA.
__global__ void __launch_bounds__(NTHR) k_fwd1(const float* __restrict__ f, int nb){
    __shared__ float2 s[48*LDP];
    __shared__ float2 tw[48];
    init_tw(tw);
    int b = blockIdx.x / 48, x = blockIdx.x % 48;
    const float* src = f + (size_t)b*N3 + x*N2P;
    for (int i = threadIdx.x; i < N2P; i += NTHR){
        int y = i/48, z = i%48;
        float sg = ((x + y + z) & 1) ? -1.0f : 1.0f;
        s[y*LDP + z] = make_float2(sg * src[i], 0.0f);
    }
    __syncthreads();
    fft_lines<1,  LDP>(s, tw);   // z-lines
    fft_lines<LDP, 1 >(s, tw);   // y-lines
    float2* dst = g_spec + (size_t)b*N3 + x*N2P;
    for (int i = threadIdx.x; i < N2P; i += NTHR){
        int y = i/48, z = i%48;
        dst[i] = s[y*LDP + z];
    }
}

// K2: FFT along x, scale by 1/N^3, in place -> f_spec. One (x,z) plane per CTA.
__global__ void __launch_bounds__(NTHR) k_fwd2(int nb){
    __shared__ float2 s[48*LDP];
    __shared__ float2 tw[48];
    init_tw(tw);
    int b = blockIdx.x / 48, y = blockIdx.x % 48;
    float2* base = g_spec + (size_t)b*N3 + y*48;
    for (int i = threadIdx.x; i < N2P; i += NTHR){
        int x = i/48, z = i%48;
        s[x*LDP + z] = base[x*N2P + z];
    }
    __syncthreads();
    fft_lines<LDP, 1>(s, tw);    // x-lines
    const float inv = 1.0f / (float)N3;
    for (int i = threadIdx.x; i < N2P; i += NTHR){
        int x = i/48, z = i%48;
        float2 v = s[x*LDP + z];
        base[x*N2P + z] = make_float2(v.x*inv, v.y*inv);
    }
}

// K3: u = f_spec * w_j, FFT z then y. j in [0,42): phi_t / psi_t / phipsi / 1.
__global__ void __launch_bounds__(NTHR) k_mulfft(const float* __restrict__ phi,
                                                 const float* __restrict__ psi,
                                                 const float* __restrict__ phipsi){
    __shared__ float2 s[48*LDP];
    __shared__ float2 tw[48];
    init_tw(tw);
    int vol = blockIdx.x / 48, x = blockIdx.x % 48;
    int b = vol / NJ, j = vol % NJ;
    const float2* fs = g_spec + (size_t)b*N3 + x*N2P;
    const float* w;
    if      (j < 20) w = phi    + (size_t)j*N3       + x*N2P;
    else if (j < 40) w = psi    + (size_t)(j-20)*N3  + x*N2P;
    else if (j == 40) w = phipsi + x*N2P;
    else              w = nullptr;
    for (int i = threadIdx.x; i < N2P; i += NTHR){
        int y = i/48, z = i%48;
        float2 v = fs[i];
        float wv = w ? w[i] : 1.0f;
        s[y*LDP + z] = make_float2(v.x*wv, v.y*wv);
    }
    __syncthreads();
    fft_lines<1,  LDP>(s, tw);
    fft_lines<LDP, 1 >(s, tw);
    float2* dst = g_S + (size_t)vol*N3 + x*N2P;
    for (int i = threadIdx.x; i < N2P; i += NTHR){
        int y = i/48, z = i%48;
        dst[i] = s[y*LDP + z];
    }
}

// K4: per (b,y) plane, finish x-FFT for all 21 (G,H) pairs and accumulate
//     Re(G*H) with sign (+ for the 20 phi/psi pairs, - for the fl pair).
__global__ void __launch_bounds__(NTHR) k_final(float* __restrict__ Q,
                                                const float* __restrict__ kn){
    __shared__ float2 sG[48*LDP];
    __shared__ float2 sH[48*LDP];
    __shared__ float  acc[48*48];
    __shared__ float2 tw[48];
    init_tw(tw);
    for (int i = threadIdx.x; i < N2P; i += NTHR) acc[i] = 0.0f;
    int b = blockIdx.x / 48, y = blockIdx.x % 48;
    __syncthreads();

    for (int p = 0; p < 21; p++){
        int jG = (p < 20) ? p      : 40;
        int jH = (p < 20) ? 20 + p : 41;
        float sgn = (p < 20) ? 1.0f : -1.0f;
        const float2* srcG = g_S + (size_t)(b*NJ + jG)*N3 + y*48;
        const float2* srcH = g_S + (size_t)(b*NJ + jH)*N3 + y*48;
        for (int i = threadIdx.x; i < N2P; i += NTHR){
            int x = i/48, z = i%48;
            sG[x*LDP + z] = srcG[x*N2P + z];
            sH[x*LDP + z] = srcH[x*N2P + z];
        }
        __syncthreads();
        fft_lines<LDP, 1>(sG, tw);   // x-lines
        fft_lines<LDP, 1>(sH, tw);
        for (int i = threadIdx.x; i < N2P; i += NTHR){
            int x = i/48, z = i%48;
            float2 gv = sG[x*LDP + z], hv = sH[x*LDP + z];
            acc[i] += sgn * (gv.x*hv.x - gv.y*hv.y);
        }
        __syncthreads();   // protect sG/sH before next pair's loads
    }

    // scale = 4*pi^2 / kn_bzm / M^2 ; M is fixed at 5 by the problem setup.
    const float scale = 4.0f*PI_F*PI_F / (kn[0] * 25.0f);
    float* dst = Q + (size_t)b*N3 + y*48;
    for (int i = threadIdx.x; i < N2P; i += NTHR){
        int x = i/48, z = i%48;
        dst[x*N2P + z] = scale * acc[i];
    }
}

extern "C" void kernel_launch(void* const* d_in, const int* in_sizes, int n_in,
                              void* d_out, int out_size){
    const float* f      = (const float*)d_in[0];
    const float* kn     = (const float*)d_in[1];
    const float* phi    = (const float*)d_in[2];
    const float* psi    = (const float*)d_in[3];
    const float* phipsi = (const float*)d_in[4];
    float* Q = (float*)d_out;

    int nb = in_sizes[0] / N3;   // = 8
    if (nb > NB) nb = NB;

    k_fwd1  <<<nb*48,      NTHR>>>(f, nb);
    k_fwd2  <<<nb*48,      NTHR>>>(nb);
    k_mulfft<<<nb*NJ*48,   NTHR>>>(phi, psi, phipsi);
    k_final <<<nb*48,      NTHR>>>(Q, kn);
}

// round 2
// speedup vs baseline: 1.2880x; 1.2880x over previous
#include <cuda_runtime.h>
#include <cstdint>

// ---------------------------------------------------------------------------
// Boltzmann collision operator, spectral method. N=48, B=8, M=5 -> 20 modes.
//   Q = scale * Re( sum_t FFT(fs*phi_t)*FFT(fs*psi_t) - FFT(fs*phipsi)*FFT(fs) )
//   fs = fftshift(FFT3(f))/N^3  (fftshift folded into (-1)^(x+y+z) input flip)
// Round 2: pair-parallel final stage + partial buffer + fused dual-plane FFT
//          + batch-fastest ordering in k_mulfft for weight L2 reuse.
// ---------------------------------------------------------------------------

#define NN    48
#define N2P   (NN*NN)        // 2304
#define N3    (NN*NN*NN)     // 110592
#define NB    8
#define NJ    42             // 20 phi + 20 psi + phipsi + identity
#define NPAIR 21
#define LDP   49             // padded smem row (float2 units)
#define NTHR  384
#define PI_F  3.14159265358979323846f

// scratch (__device__ globals; no runtime allocation)
__device__ float2 g_spec[NB * N3];                    // ~7 MB
__device__ float2 g_S[(size_t)NB * NJ * N3];          // ~297 MB
__device__ float  g_part[(size_t)NPAIR * NB * N3];    // ~74 MB signed partials

__device__ __forceinline__ float2 cadd(float2 a, float2 b){ return make_float2(a.x+b.x, a.y+b.y); }
__device__ __forceinline__ float2 csub(float2 a, float2 b){ return make_float2(a.x-b.x, a.y-b.y); }
__device__ __forceinline__ float2 cmul(float2 a, float2 b){
    return make_float2(a.x*b.x - a.y*b.y, a.x*b.y + a.y*b.x);
}

__device__ __forceinline__ void dft3(float2 a, float2 b, float2 c,
                                     float2& X0, float2& X1, float2& X2){
    float2 t1 = cadd(b, c);
    X0 = cadd(a, t1);
    float2 m = make_float2(a.x - 0.5f*t1.x, a.y - 0.5f*t1.y);
    const float K = 0.8660254037844386f;
    float2 s = make_float2(K*(b.x - c.x), K*(b.y - c.y));
    X1 = make_float2(m.x + s.y, m.y - s.x);   // m - i*s
    X2 = make_float2(m.x - s.y, m.y + s.x);   // m + i*s
}

// ---- stage A: DFT6 over n1 (stride 8) + twiddle; thread-private slots ------
template <int LDR, int LDL>
__device__ __forceinline__ void stageA(float2* s, const float2* tw){
    const int w = threadIdx.x;
    int line = w >> 3, n2 = w & 7;
    float2* base = s + line*LDL + n2*LDR;
    float2 x0 = base[0*8*LDR], x1 = base[1*8*LDR], x2 = base[2*8*LDR];
    float2 x3 = base[3*8*LDR], x4 = base[4*8*LDR], x5 = base[5*8*LDR];
    float2 E0,E1,E2, O0,O1,O2;
    dft3(x0, x2, x4, E0, E1, E2);
    dft3(x1, x3, x5, O0, O1, O2);
    const float K = 0.8660254037844386f;
    float2 o1 = cmul(O1, make_float2( 0.5f, -K));
    float2 o2 = cmul(O2, make_float2(-0.5f, -K));
    float2 y0 = cadd(E0, O0), y3 = csub(E0, O0);
    float2 y1 = cadd(E1, o1), y4 = csub(E1, o1);
    float2 y2 = cadd(E2, o2), y5 = csub(E2, o2);
    const float2* t = tw + n2*6;
    y1 = cmul(y1, t[1]); y2 = cmul(y2, t[2]); y3 = cmul(y3, t[3]);
    y4 = cmul(y4, t[4]); y5 = cmul(y5, t[5]);
    base[0*8*LDR] = y0; base[1*8*LDR] = y1; base[2*8*LDR] = y2;
    base[3*8*LDR] = y3; base[4*8*LDR] = y4; base[5*8*LDR] = y5;
}

// ---- stage B pieces: gather 8, DFT8, scatter at stride 6 -------------------
template <int LDR, int LDL>
__device__ __forceinline__ void stageB_load(const float2* s, int line, int k1, float2* r){
    const float2* base = s + line*LDL + (k1*8)*LDR;
    #pragma unroll
    for (int i = 0; i < 8; i++) r[i] = base[i*LDR];
}
__device__ __forceinline__ void dft8(const float2* r, float2* o){
    float2 t0 = cadd(r[0],r[4]), t1 = csub(r[0],r[4]);
    float2 t2 = cadd(r[2],r[6]), t3 = csub(r[2],r[6]);
    float2 E0 = cadd(t0,t2), E2 = csub(t0,t2);
    float2 E1 = make_float2(t1.x + t3.y, t1.y - t3.x);
    float2 E3 = make_float2(t1.x - t3.y, t1.y + t3.x);
    float2 u0 = cadd(r[1],r[5]), u1 = csub(r[1],r[5]);
    float2 u2 = cadd(r[3],r[7]), u3 = csub(r[3],r[7]);
    float2 Q0 = cadd(u0,u2), Q2 = csub(u0,u2);
    float2 Q1 = make_float2(u1.x + u3.y, u1.y - u3.x);
    float2 Q3 = make_float2(u1.x - u3.y, u1.y + u3.x);
    const float S2 = 0.7071067811865476f;
    float2 p1 = cmul(Q1, make_float2( S2, -S2));
    float2 p2 = make_float2(Q2.y, -Q2.x);
    float2 p3 = cmul(Q3, make_float2(-S2, -S2));
    o[0] = cadd(E0,Q0); o[1] = cadd(E1,p1); o[2] = cadd(E2,p2); o[3] = cadd(E3,p3);
    o[4] = csub(E0,Q0); o[5] = csub(E1,p1); o[6] = csub(E2,p2); o[7] = csub(E3,p3);
}
template <int LDR, int LDL>
__device__ __forceinline__ void stageB_store(float2* s, int line, int k1, const float2* o){
    float2* out = s + line*LDL + k1*LDR;
    #pragma unroll
    for (int i = 0; i < 8; i++) out[(i*6)*LDR] = o[i];
}

// single-plane 48x FFT48 (stage A + stage B, in place)
template <int LDR, int LDL>
__device__ void fft_lines(float2* s, const float2* tw){
    stageA<LDR,LDL>(s, tw);
    __syncthreads();
    const int w = threadIdx.x;
    int line = w % 48, k1 = w / 48;
    bool act = (w < 288);
    float2 r[8];
    if (act) stageB_load<LDR,LDL>(s, line, k1, r);
    __syncthreads();
    if (act){
        float2 o[8];
        dft8(r, o);
        stageB_store<LDR,LDL>(s, line, k1, o);
    }
    __syncthreads();
}

// dual-plane 48x FFT48: both planes share the barrier set (half the syncs)
template <int LDR, int LDL>
__device__ void fft_lines2(float2* sA, float2* sB, const float2* tw){
    stageA<LDR,LDL>(sA, tw);
    stageA<LDR,LDL>(sB, tw);
    __syncthreads();
    const int w = threadIdx.x;
    int line = w % 48, k1 = w / 48;
    bool act = (w < 288);
    float2 ra[8], rb[8];
    if (act){
        stageB_load<LDR,LDL>(sA, line, k1, ra);
        stageB_load<LDR,LDL>(sB, line, k1, rb);
    }
    __syncthreads();
    if (act){
        float2 oa[8], ob[8];
        dft8(ra, oa);
        dft8(rb, ob);
        stageB_store<LDR,LDL>(sA, line, k1, oa);
        stageB_store<LDR,LDL>(sB, line, k1, ob);
    }
    __syncthreads();
}

__device__ __forceinline__ void init_tw(float2* tw){
    if (threadIdx.x < 48){
        int n2 = threadIdx.x / 6, k1 = threadIdx.x % 6;
        float sv, cv;
        sincosf(-2.0f*PI_F * (float)(n2*k1) / 48.0f, &sv, &cv);
        tw[threadIdx.x] = make_float2(cv, sv);
    }
}

// K1: f * (-1)^(x+y+z), FFT along z then y; one x-plane per CTA.
__global__ void __launch_bounds__(NTHR) k_fwd1(const float* __restrict__ f){
    __shared__ float2 s[48*LDP];
    __shared__ float2 tw[48];
    init_tw(tw);
    int b = blockIdx.x / 48, x = blockIdx.x % 48;
    const float* src = f + (size_t)b*N3 + x*N2P;
    for (int i = threadIdx.x; i < N2P; i += NTHR){
        int y = i/48, z = i%48;
        float sg = ((x + y + z) & 1) ? -1.0f : 1.0f;
        s[y*LDP + z] = make_float2(sg * src[i], 0.0f);
    }
    __syncthreads();
    fft_lines<1,  LDP>(s, tw);   // z-lines
    fft_lines<LDP, 1 >(s, tw);   // y-lines
    float2* dst = g_spec + (size_t)b*N3 + x*N2P;
    for (int i = threadIdx.x; i < N2P; i += NTHR){
        int y = i/48, z = i%48;
        dst[i] = s[y*LDP + z];
    }
}

// K2: FFT along x, scale by 1/N^3, in place. One y-plane per CTA.
__global__ void __launch_bounds__(NTHR) k_fwd2(){
    __shared__ float2 s[48*LDP];
    __shared__ float2 tw[48];
    init_tw(tw);
    int b = blockIdx.x / 48, y = blockIdx.x % 48;
    float2* base = g_spec + (size_t)b*N3 + y*48;
    for (int i = threadIdx.x; i < N2P; i += NTHR){
        int x = i/48, z = i%48;
        s[x*LDP + z] = base[x*N2P + z];
    }
    __syncthreads();
    fft_lines<LDP, 1>(s, tw);    // x-lines
    const float inv = 1.0f / (float)N3;
    for (int i = threadIdx.x; i < N2P; i += NTHR){
        int x = i/48, z = i%48;
        float2 v = s[x*LDP + z];
        base[x*N2P + z] = make_float2(v.x*inv, v.y*inv);
    }
}

// K3: u = f_spec * w_j, FFT z then y.  Batch varies fastest in blockIdx so the
//     ~384 concurrently-resident CTAs of one j share one 0.44MB weight volume
//     in L2 (weight DRAM traffic 147MB -> ~18MB).
__global__ void __launch_bounds__(NTHR) k_mulfft(const float* __restrict__ phi,
                                                 const float* __restrict__ psi,
                                                 const float* __restrict__ phipsi,
                                                 int nb){
    __shared__ float2 s[48*LDP];
    __shared__ float2 tw[48];
    init_tw(tw);
    int x = blockIdx.x % 48;
    int bv = blockIdx.x / 48;
    int b = bv % nb;
    int j = bv / nb;
    const float2* fs = g_spec + (size_t)b*N3 + x*N2P;
    const float* w;
    if      (j < 20)  w = phi    + (size_t)j*N3      + x*N2P;
    else if (j < 40)  w = psi    + (size_t)(j-20)*N3 + x*N2P;
    else if (j == 40) w = phipsi + x*N2P;
    else              w = nullptr;
    for (int i = threadIdx.x; i < N2P; i += NTHR){
        int y = i/48, z = i%48;
        float2 v = fs[i];
        float wv = w ? w[i] : 1.0f;
        s[y*LDP + z] = make_float2(v.x*wv, v.y*wv);
    }
    __syncthreads();
    fft_lines<1,  LDP>(s, tw);
    fft_lines<LDP, 1 >(s, tw);
    float2* dst = g_S + (size_t)(b*NJ + j)*N3 + x*N2P;
    for (int i = threadIdx.x; i < N2P; i += NTHR){
        int y = i/48, z = i%48;
        dst[i] = s[y*LDP + z];
    }
}

// K4: one (pair p, batch b, y-plane) per CTA. Finish x-FFT for the G and H
//     planes together, write signed Re(G*H) partial. 21x more CTAs than before.
__global__ void __launch_bounds__(NTHR) k_pair(int nb){
    __shared__ float2 sG[48*LDP];
    __shared__ float2 sH[48*LDP];
    __shared__ float2 tw[48];
    init_tw(tw);
    int y  = blockIdx.x % 48;
    int bv = blockIdx.x / 48;
    int b  = bv % nb;
    int p  = bv / nb;
    int jG = (p < 20) ? p      : 40;
    int jH = (p < 20) ? 20 + p : 41;
    float sgn = (p < 20) ? 1.0f : -1.0f;
    const float2* srcG = g_S + (size_t)(b*NJ + jG)*N3 + y*48;
    const float2* srcH = g_S + (size_t)(b*NJ + jH)*N3 + y*48;
    for (int i = threadIdx.x; i < N2P; i += NTHR){
        int x = i/48, z = i%48;
        sG[x*LDP + z] = srcG[x*N2P + z];
        sH[x*LDP + z] = srcH[x*N2P + z];
    }
    __syncthreads();
    fft_lines2<LDP, 1>(sG, sH, tw);  // x-lines, both planes, shared barriers
    float* dst = g_part + (size_t)(p*NB + b)*N3 + y*48;
    for (int i = threadIdx.x; i < N2P; i += NTHR){
        int x = i/48, z = i%48;
        float2 gv = sG[x*LDP + z], hv = sH[x*LDP + z];
        dst[x*N2P + z] = sgn * (gv.x*hv.x - gv.y*hv.y);
    }
}

// K5: deterministic combine: Q = scale * sum_p partial_p.
__global__ void __launch_bounds__(256) k_combine(float* __restrict__ Q,
                                                 const float* __restrict__ kn,
                                                 int nb){
    int idx = blockIdx.x * 256 + threadIdx.x;
    int total = nb * N3;
    if (idx >= total) return;
    int b = idx / N3, i = idx % N3;
    const float* src = g_part + (size_t)b*N3 + i;
    float acc = 0.0f;
    #pragma unroll
    for (int p = 0; p < NPAIR; p++)
        acc += src[(size_t)p*NB*N3];
    const float scale = 4.0f*PI_F*PI_F / (kn[0] * 25.0f);
    Q[idx] = scale * acc;
}

extern "C" void kernel_launch(void* const* d_in, const int* in_sizes, int n_in,
                              void* d_out, int out_size){
    const float* f      = (const float*)d_in[0];
    const float* kn     = (const float*)d_in[1];
    const float* phi    = (const float*)d_in[2];
    const float* psi    = (const float*)d_in[3];
    const float* phipsi = (const float*)d_in[4];
    float* Q = (float*)d_out;

    int nb = in_sizes[0] / N3;   // = 8
    if (nb > NB) nb = NB;

    k_fwd1  <<<nb*48,          NTHR>>>(f);
    k_fwd2  <<<nb*48,          NTHR>>>();
    k_mulfft<<<NJ*nb*48,       NTHR>>>(phi, psi, phipsi, nb);
    k_pair  <<<NPAIR*nb*48,    NTHR>>>(nb);
    k_combine<<<(nb*N3+255)/256, 256>>>(Q, kn, nb);
}

// round 3
// speedup vs baseline: 1.6747x; 1.3002x over previous
#include <cuda_runtime.h>
#include <cstdint>

// ---------------------------------------------------------------------------
// Boltzmann collision operator, spectral method. N=48, B=8, M=5 -> 20 modes.
//   Q = scale * Re( sum_t FFT(fs*phi_t)*FFT(fs*psi_t) - FFT(fs*phipsi)*FFT(fs) )
//   fs = fftshift(FFT3(f))/N^3  (fftshift folded into (-1)^(x+y+z) input flip)
// Round 3: register-fused pair product (no stage-B smem round trip),
//          3-pair register accumulation (7 partial slabs), dual-plane mulfft
//          with direct stage-B global stores, float4 loads.
// ---------------------------------------------------------------------------

#define NN    48
#define N2P   (NN*NN)        // 2304
#define N3    (NN*NN*NN)     // 110592
#define NB    8
#define NJ    42             // 20 phi + 20 psi + phipsi + identity
#define NPG   3              // pairs per k_pair CTA
#define NGRP  7              // 21 / NPG partial slabs
#define LDP   49             // padded smem row (float2 units)
#define NTHR  384
#define PI_F  3.14159265358979323846f

// scratch (__device__ globals; no runtime allocation)
__device__ float2 g_spec[NB * N3];                    // ~7 MB
__device__ float2 g_S[(size_t)NB * NJ * N3];          // ~297 MB
__device__ float  g_part[(size_t)NGRP * NB * N3];     // ~25 MB signed partials

__device__ __forceinline__ float2 cadd(float2 a, float2 b){ return make_float2(a.x+b.x, a.y+b.y); }
__device__ __forceinline__ float2 csub(float2 a, float2 b){ return make_float2(a.x-b.x, a.y-b.y); }
__device__ __forceinline__ float2 cmul(float2 a, float2 b){
    return make_float2(a.x*b.x - a.y*b.y, a.x*b.y + a.y*b.x);
}

__device__ __forceinline__ void dft3(float2 a, float2 b, float2 c,
                                     float2& X0, float2& X1, float2& X2){
    float2 t1 = cadd(b, c);
    X0 = cadd(a, t1);
    float2 m = make_float2(a.x - 0.5f*t1.x, a.y - 0.5f*t1.y);
    const float K = 0.8660254037844386f;
    float2 s = make_float2(K*(b.x - c.x), K*(b.y - c.y));
    X1 = make_float2(m.x + s.y, m.y - s.x);   // m - i*s
    X2 = make_float2(m.x - s.y, m.y + s.x);   // m + i*s
}

// ---- stage A: DFT6 over n1 (stride 8) + twiddle; thread-private slots ------
template <int LDR, int LDL>
__device__ __forceinline__ void stageA(float2* s, const float2* tw){
    const int w = threadIdx.x;
    int line = w >> 3, n2 = w & 7;
    float2* base = s + line*LDL + n2*LDR;
    float2 x0 = base[0*8*LDR], x1 = base[1*8*LDR], x2 = base[2*8*LDR];
    float2 x3 = base[3*8*LDR], x4 = base[4*8*LDR], x5 = base[5*8*LDR];
    float2 E0,E1,E2, O0,O1,O2;
    dft3(x0, x2, x4, E0, E1, E2);
    dft3(x1, x3, x5, O0, O1, O2);
    const float K = 0.8660254037844386f;
    float2 o1 = cmul(O1, make_float2( 0.5f, -K));
    float2 o2 = cmul(O2, make_float2(-0.5f, -K));
    float2 y0 = cadd(E0, O0), y3 = csub(E0, O0);
    float2 y1 = cadd(E1, o1), y4 = csub(E1, o1);
    float2 y2 = cadd(E2, o2), y5 = csub(E2, o2);
    const float2* t = tw + n2*6;
    y1 = cmul(y1, t[1]); y2 = cmul(y2, t[2]); y3 = cmul(y3, t[3]);
    y4 = cmul(y4, t[4]); y5 = cmul(y5, t[5]);
    base[0*8*LDR] = y0; base[1*8*LDR] = y1; base[2*8*LDR] = y2;
    base[3*8*LDR] = y3; base[4*8*LDR] = y4; base[5*8*LDR] = y5;
}

// ---- stage B pieces ---------------------------------------------------------
template <int LDR, int LDL>
__device__ __forceinline__ void stageB_load(const float2* s, int line, int k1, float2* r){
    const float2* base = s + line*LDL + (k1*8)*LDR;
    #pragma unroll
    for (int i = 0; i < 8; i++) r[i] = base[i*LDR];
}
__device__ __forceinline__ void dft8(const float2* r, float2* o){
    float2 t0 = cadd(r[0],r[4]), t1 = csub(r[0],r[4]);
    float2 t2 = cadd(r[2],r[6]), t3 = csub(r[2],r[6]);
    float2 E0 = cadd(t0,t2), E2 = csub(t0,t2);
    float2 E1 = make_float2(t1.x + t3.y, t1.y - t3.x);
    float2 E3 = make_float2(t1.x - t3.y, t1.y + t3.x);
    float2 u0 = cadd(r[1],r[5]), u1 = csub(r[1],r[5]);
    float2 u2 = cadd(r[3],r[7]), u3 = csub(r[3],r[7]);
    float2 Q0 = cadd(u0,u2), Q2 = csub(u0,u2);
    float2 Q1 = make_float2(u1.x + u3.y, u1.y - u3.x);
    float2 Q3 = make_float2(u1.x - u3.y, u1.y + u3.x);
    const float S2 = 0.7071067811865476f;
    float2 p1 = cmul(Q1, make_float2( S2, -S2));
    float2 p2 = make_float2(Q2.y, -Q2.x);
    float2 p3 = cmul(Q3, make_float2(-S2, -S2));
    o[0] = cadd(E0,Q0); o[1] = cadd(E1,p1); o[2] = cadd(E2,p2); o[3] = cadd(E3,p3);
    o[4] = csub(E0,Q0); o[5] = csub(E1,p1); o[6] = csub(E2,p2); o[7] = csub(E3,p3);
}
template <int LDR, int LDL>
__device__ __forceinline__ void stageB_store(float2* s, int line, int k1, const float2* o){
    float2* out = s + line*LDL + k1*LDR;
    #pragma unroll
    for (int i = 0; i < 8; i++) out[(i*6)*LDR] = o[i];
}

// single-plane full FFT pass (in place)
template <int LDR, int LDL>
__device__ void fft_lines(float2* s, const float2* tw){
    stageA<LDR,LDL>(s, tw);
    __syncthreads();
    const int w = threadIdx.x;
    int line = w % 48, k1 = w / 48;
    bool act = (w < 288);
    float2 r[8];
    if (act) stageB_load<LDR,LDL>(s, line, k1, r);
    __syncthreads();
    if (act){
        float2 o[8];
        dft8(r, o);
        stageB_store<LDR,LDL>(s, line, k1, o);
    }
    __syncthreads();
}

// dual-plane full FFT pass, in place, shared barriers
template <int LDR, int LDL>
__device__ void fft_lines2(float2* sA, float2* sB, const float2* tw){
    stageA<LDR,LDL>(sA, tw);
    stageA<LDR,LDL>(sB, tw);
    __syncthreads();
    const int w = threadIdx.x;
    int line = w % 48, k1 = w / 48;
    bool act = (w < 288);
    float2 ra[8], rb[8];
    if (act){
        stageB_load<LDR,LDL>(sA, line, k1, ra);
        stageB_load<LDR,LDL>(sB, line, k1, rb);
    }
    __syncthreads();
    if (act){
        float2 oa[8], ob[8];
        dft8(ra, oa);
        dft8(rb, ob);
        stageB_store<LDR,LDL>(sA, line, k1, oa);
        stageB_store<LDR,LDL>(sB, line, k1, ob);
    }
    __syncthreads();
}

__device__ __forceinline__ void init_tw(float2* tw){
    if (threadIdx.x < 48){
        int n2 = threadIdx.x / 6, k1 = threadIdx.x % 6;
        float sv, cv;
        sincosf(-2.0f*PI_F * (float)(n2*k1) / 48.0f, &sv, &cv);
        tw[threadIdx.x] = make_float2(cv, sv);
    }
}

// K1: f * (-1)^(x+y+z), FFT along z then y; one x-plane per CTA.
__global__ void __launch_bounds__(NTHR) k_fwd1(const float* __restrict__ f){
    __shared__ float2 s[48*LDP];
    __shared__ float2 tw[48];
    init_tw(tw);
    int b = blockIdx.x / 48, x = blockIdx.x % 48;
    const float* src = f + (size_t)b*N3 + x*N2P;
    for (int i = threadIdx.x; i < N2P; i += NTHR){
        int y = i/48, z = i%48;
        float sg = ((x + y + z) & 1) ? -1.0f : 1.0f;
        s[y*LDP + z] = make_float2(sg * src[i], 0.0f);
    }
    __syncthreads();
    fft_lines<1,  LDP>(s, tw);   // z-lines
    fft_lines<LDP, 1 >(s, tw);   // y-lines
    float2* dst = g_spec + (size_t)b*N3 + x*N2P;
    for (int i = threadIdx.x; i < N2P; i += NTHR){
        int y = i/48, z = i%48;
        dst[i] = s[y*LDP + z];
    }
}

// K2: FFT along x, scale by 1/N^3, in place. One y-plane per CTA.
__global__ void __launch_bounds__(NTHR) k_fwd2(){
    __shared__ float2 s[48*LDP];
    __shared__ float2 tw[48];
    init_tw(tw);
    int b = blockIdx.x / 48, y = blockIdx.x % 48;
    float2* base = g_spec + (size_t)b*N3 + y*48;
    for (int i = threadIdx.x; i < N2P; i += NTHR){
        int x = i/48, z = i%48;
        s[x*LDP + z] = base[x*N2P + z];
    }
    __syncthreads();
    fft_lines<LDP, 1>(s, tw);    // x-lines
    const float inv = 1.0f / (float)N3;
    for (int i = threadIdx.x; i < N2P; i += NTHR){
        int x = i/48, z = i%48;
        float2 v = s[x*LDP + z];
        base[x*N2P + z] = make_float2(v.x*inv, v.y*inv);
    }
}

// K3: dual-plane: uG = fs*phi_t, uH = fs*psi_t (or phipsi / identity).
//     FFT z-lines (in place), then y-lines with stage-B registers written
//     STRAIGHT to global (skips final smem store + read + one barrier).
//     Batch varies fastest so concurrent CTAs of one p share weights in L2.
__global__ void __launch_bounds__(NTHR) k_mulfft(const float* __restrict__ phi,
                                                 const float* __restrict__ psi,
                                                 const float* __restrict__ phipsi,
                                                 int nb){
    __shared__ float2 sG[48*LDP];
    __shared__ float2 sH[48*LDP];
    __shared__ float2 tw[48];
    init_tw(tw);
    int x  = blockIdx.x % 48;
    int bv = blockIdx.x / 48;
    int b  = bv % nb;
    int p  = bv / nb;            // 0..20
    int jG = (p < 20) ? p      : 40;
    int jH = (p < 20) ? 20 + p : 41;
    const float2* fs = g_spec + (size_t)b*N3 + x*N2P;
    const float* wG = (p < 20) ? (phi + (size_t)p*N3 + x*N2P) : (phipsi + (size_t)x*N2P);
    const float* wH = (p < 20) ? (psi + (size_t)p*N3 + x*N2P) : nullptr;

    // load fs as float4 (2 complex), weights as float2 (2 floats)
    for (int i = threadIdx.x; i < N2P/2; i += NTHR){
        int y = i/24, q = i%24;
        int z0 = q*2;
        float4 fv = *(const float4*)(fs + y*48 + z0);
        float2 wg = *(const float2*)(wG + y*48 + z0);
        float2 wh = wH ? *(const float2*)(wH + y*48 + z0) : make_float2(1.0f, 1.0f);
        sG[y*LDP + z0    ] = make_float2(fv.x*wg.x, fv.y*wg.x);
        sG[y*LDP + z0 + 1] = make_float2(fv.z*wg.y, fv.w*wg.y);
        sH[y*LDP + z0    ] = make_float2(fv.x*wh.x, fv.y*wh.x);
        sH[y*LDP + z0 + 1] = make_float2(fv.z*wh.y, fv.w*wh.y);
    }
    __syncthreads();
    fft_lines2<1, LDP>(sG, sH, tw);      // z-lines, in place

    // y-lines: stage A in place, stage B -> global
    stageA<LDP,1>(sG, tw);
    stageA<LDP,1>(sH, tw);
    __syncthreads();
    const int w = threadIdx.x;
    if (w < 288){
        int line = w % 48, k1 = w / 48;   // line = z
        float2 ra[8], rb[8], oa[8], ob[8];
        stageB_load<LDP,1>(sG, line, k1, ra);
        stageB_load<LDP,1>(sH, line, k1, rb);
        dft8(ra, oa);
        dft8(rb, ob);
        float2* dstG = g_S + (size_t)(b*NJ + jG)*N3 + x*N2P;
        float2* dstH = g_S + (size_t)(b*NJ + jH)*N3 + x*N2P;
        #pragma unroll
        for (int i = 0; i < 8; i++){
            int y = k1 + 6*i;
            dstG[y*48 + line] = oa[i];
            dstH[y*48 + line] = ob[i];
        }
    }
}

// K4: one (group g of NPG pairs, batch b, y-plane) per CTA.
//     Per pair: load G,H planes, x-FFT stage A (smem), stage B in registers,
//     product accumulated in registers across the NPG pairs, single store.
__global__ void __launch_bounds__(NTHR) k_pair(int nb){
    __shared__ float2 sG[48*LDP];
    __shared__ float2 sH[48*LDP];
    __shared__ float2 tw[48];
    init_tw(tw);
    int y  = blockIdx.x % 48;
    int bv = blockIdx.x / 48;
    int b  = bv % nb;
    int g  = bv / nb;            // 0..6
    const int w = threadIdx.x;
    const int line = w % 48, k1 = w / 48;
    const bool act = (w < 288);
    float acc[8];
    #pragma unroll
    for (int i = 0; i < 8; i++) acc[i] = 0.0f;

    for (int pp = 0; pp < NPG; pp++){
        int p  = g*NPG + pp;
        int jG = (p < 20) ? p      : 40;
        int jH = (p < 20) ? 20 + p : 41;
        float sgn = (p < 20) ? 1.0f : -1.0f;
        const float2* srcG = g_S + (size_t)(b*NJ + jG)*N3 + y*48;
        const float2* srcH = g_S + (size_t)(b*NJ + jH)*N3 + y*48;
        for (int i = threadIdx.x; i < N2P/2; i += NTHR){
            int x = i/24, q = i%24;
            int z0 = q*2;
            float4 gv = *(const float4*)(srcG + x*N2P + z0);
            float4 hv = *(const float4*)(srcH + x*N2P + z0);
            sG[x*LDP + z0    ] = make_float2(gv.x, gv.y);
            sG[x*LDP + z0 + 1] = make_float2(gv.z, gv.w);
            sH[x*LDP + z0    ] = make_float2(hv.x, hv.y);
            sH[x*LDP + z0 + 1] = make_float2(hv.z, hv.w);
        }
        __syncthreads();
        // x-lines: element stride LDP, line (=z) stride 1
        stageA<LDP,1>(sG, tw);
        stageA<LDP,1>(sH, tw);
        __syncthreads();
        if (act){
            float2 ra[8], rb[8], oa[8], ob[8];
            stageB_load<LDP,1>(sG, line, k1, ra);
            stageB_load<LDP,1>(sH, line, k1, rb);
            dft8(ra, oa);
            dft8(rb, ob);
            #pragma unroll
            for (int i = 0; i < 8; i++)
                acc[i] += sgn * (oa[i].x*ob[i].x - oa[i].y*ob[i].y);
        }
        __syncthreads();   // protect sG/sH before next pair's loads
    }

    if (act){
        float* dst = g_part + (size_t)(g*nb + b)*N3 + y*48;
        #pragma unroll
        for (int i = 0; i < 8; i++){
            int x = k1 + 6*i;
            dst[x*N2P + line] = acc[i];
        }
    }
}

// K5: deterministic combine: Q = scale * sum_g partial_g (float4).
__global__ void __launch_bounds__(256) k_combine(float* __restrict__ Q,
                                                 const float* __restrict__ kn,
                                                 int nb){
    int idx = blockIdx.x * 256 + threadIdx.x;
    int total4 = nb * N3 / 4;
    if (idx >= total4) return;
    const float4* src = (const float4*)g_part + idx;
    size_t stride4 = (size_t)nb * N3 / 4;
    float4 a = make_float4(0.f, 0.f, 0.f, 0.f);
    #pragma unroll
    for (int s = 0; s < NGRP; s++){
        float4 v = src[s*stride4];
        a.x += v.x; a.y += v.y; a.z += v.z; a.w += v.w;
    }
    const float scale = 4.0f*PI_F*PI_F / (kn[0] * 25.0f);
    ((float4*)Q)[idx] = make_float4(scale*a.x, scale*a.y, scale*a.z, scale*a.w);
}

extern "C" void kernel_launch(void* const* d_in, const int* in_sizes, int n_in,
                              void* d_out, int out_size){
    const float* f      = (const float*)d_in[0];
    const float* kn     = (const float*)d_in[1];
    const float* phi    = (const float*)d_in[2];
    const float* psi    = (const float*)d_in[3];
    const float* phipsi = (const float*)d_in[4];
    float* Q = (float*)d_out;

    int nb = in_sizes[0] / N3;   // = 8
    if (nb > NB) nb = NB;

    k_fwd1   <<<nb*48,        NTHR>>>(f);
    k_fwd2   <<<nb*48,        NTHR>>>();
    k_mulfft <<<21*nb*48,     NTHR>>>(phi, psi, phipsi, nb);
    k_pair   <<<NGRP*nb*48,   NTHR>>>(nb);
    k_combine<<<(nb*N3/4+255)/256, 256>>>(Q, kn, nb);
}